// round 8
// baseline (speedup 1.0000x reference)
#include <cuda_runtime.h>

// Entropy_70136815944310 — R8: mod-4 bin-split sliding window (24 warps/SM)
// + 3-bin KDE truncation + per-thread minimal kernel eval.
//
// x: [8,3,96,96] fp32 in [0,255]; out: same shape fp32.
//
// KDE kernel k(x,b) = e/(1+e)^2, e = exp(-10|x-b|), i0 = floor(x), f = x-i0.
// 3 kept bins: i0, i0+1, far = (f<0.5 ? i0-1 : i0+2); dropped bin mass
// <= exp(-15) = 3.1e-7 (validated R7: rel_err 2.96e-6).
//   e(i0) = E = exp(-10f); e(i0+1) = g/E; e(i0-1) = g*E; e(i0+2) = g2/E
//   (g = exp(-10), g2 = exp(-20)); far bins use k = e(1-2e), err < 3e-13.
//
// FOUR threads per column share one 256-bin histogram; thread p owns bins
// b%4 == p. The 3 kept bins are distinct mod 4 -> each value costs exactly
// one RMW on each of 3 threads; each thread computes only its own bin's e
// (3 MUFU: ex2 + 2 rcp), branchless via SELs.
// S = sum q, T2 = sum q*log q incremental; H = (S*log S' - T2)/S',
// S' = S + 1e-10. Quad combine via shfl_xor(1) + shfl_xor(2).

#define IMG      96
#define SEG      8                    // output rows per column-quad
#define NSEG     (IMG / SEG)          // 12
#define THREADS  (IMG * 4)            // 384: lanes 4c..4c+3 = column c
#define HSTRIDE  260                  // 256 + 4 pad
#define TROWS    (SEG + 4)            // 12
#define TCOLS    (IMG + 4)            // 100
#define NBINS    256
#define SMEM_BYTES ((IMG * HSTRIDE + TROWS * TCOLS) * 4)   // 104,640 B

#define G1  4.5399929762484854e-05f   // exp(-10)
#define G2  2.0611536224385578e-09f   // exp(-20)

__device__ __forceinline__ float frcp(float v) {
    float r; asm("rcp.approx.f32 %0, %1;" : "=f"(r) : "f"(v)); return r;
}
// q==0 -> 0*log(1e-37)==0 exactly; tiny negative residue -> ~1e-9, negligible
__device__ __forceinline__ float qlogq(float q) {
    return q * __logf(fmaxf(q, 1e-37f));
}

// Thread p's single owned-bin update for value x (3-bin truncated KDE).
// Returns active=false if this thread's candidate bin is the dropped far bin
// or out of range. b in [0,255] when active.
__device__ __forceinline__ bool kde_own(float x, int p, int& b, float& k) {
    float fl = floorf(x);
    int   i0 = (int)fl;
    float f  = x - fl;
    bool  lo = (f < 0.5f);
    int   d  = (p - i0) & 3;            // which of bins i0+{0,1,2,-1} is mine
    float E  = __expf(-10.f * f);
    float iE = frcp(E);
    // my bin's e-value
    float e = (d == 0) ? E
            : (d == 1) ? G1 * iE
            : (d == 2) ? G2 * iE       // bin i0+2 (kept iff f>=0.5)
                       : G1 * E;       // bin i0-1 (kept iff f<0.5)
    bool near = (d <= 1);
    float r  = frcp(1.f + e);          // wasted for far lanes; keeps issue uniform
    float kn = e * r * r;
    float kf = e - 2.f * e * e;
    k = near ? kn : kf;
    b = i0 + ((d == 3) ? -1 : d);
    bool act = near || ((d == 2) ? !lo : lo);
    return act && ((unsigned)b < (unsigned)NBINS);
}

__global__ __launch_bounds__(THREADS, 2)
void entropy_kernel(const float* __restrict__ in, float* __restrict__ out) {
    extern __shared__ float smem[];
    float* tile = smem + IMG * HSTRIDE;

    const int tid   = threadIdx.x;
    const int col   = tid >> 2;                    // column 0..95
    const int par   = tid & 3;                     // owns bins b%4 == par
    const int plane = blockIdx.y;
    const int r0    = blockIdx.x * SEG;
    const float* img = in  + (size_t)plane * IMG * IMG;
    float*       o   = out + (size_t)plane * IMG * IMG;

    // ---- tile: rows r0-2..r0+SEG+1, cols -2..97; OOB sentinel -10
    // (its bins are negative -> inactive == SAME padding's additive identity) ----
    for (int idx = tid; idx < TROWS * TCOLS; idx += THREADS) {
        int r = idx / TCOLS, c = idx % TCOLS;
        int gy = r0 + r - 2, gx = c - 2;
        float v = -10.0f;
        if ((unsigned)gy < (unsigned)IMG && (unsigned)gx < (unsigned)IMG)
            v = img[gy * IMG + gx];
        tile[idx] = v;
    }

    // ---- zero own quarter of the histogram (stride-4 scalar: per warp step
    // banks (4col + 4i + par)%32 are all distinct) ----
    float* h = smem + col * HSTRIDE;
    #pragma unroll 8
    for (int b = par; b < NBINS; b += 4)
        h[b] = 0.f;

    __syncthreads();

    // ---- build initial histogram for y = r0 ----
    #pragma unroll 1
    for (int wr = 0; wr < 5; wr++) {
        const float* trow = tile + wr * TCOLS + col;
        #pragma unroll
        for (int wc = 0; wc < 5; wc++) {
            float v = trow[wc];
            if (v >= 0.f) {
                int b; float k;
                if (kde_own(v, par, b, k)) h[b] += k;
            }
        }
    }

    // ---- initial scan of owned bins: S, T2 ----
    float S = 0.f, T2 = 0.f;
    #pragma unroll 8
    for (int b = par; b < NBINS; b += 4) {
        float q = h[b];
        S  += q;
        T2 += qlogq(q);
    }

    {
        float St = S, Tt = T2;
        St += __shfl_xor_sync(0xffffffffu, St, 1);
        Tt += __shfl_xor_sync(0xffffffffu, Tt, 1);
        St += __shfl_xor_sync(0xffffffffu, St, 2);
        Tt += __shfl_xor_sync(0xffffffffu, Tt, 2);
        float Sp = St + 1e-10f;
        if (par == 0)
            o[r0 * IMG + col] = __fdividef(St * __logf(Sp) - Tt, Sp);
    }

    // ---- slide down: remove tile row step-1, add tile row step+4 ----
    #pragma unroll 1
    for (int step = 1; step < SEG; step++) {
        const float* rem = tile + (step - 1) * TCOLS + col;
        const float* add = tile + (step + 4) * TCOLS + col;

        float Sr = 0.f, Tr = 0.f;     // local accumulators: short FADD chains
        #pragma unroll
        for (int wc = 0; wc < 5; wc++) {
            float v = rem[wc];
            if (v >= 0.f) {
                int b; float k;
                if (kde_own(v, par, b, k)) {
                    float q = h[b], qn = q - k;
                    h[b] = qn;
                    Tr += qlogq(qn) - qlogq(q);
                    Sr -= k;
                }
            }
        }
        #pragma unroll
        for (int wc = 0; wc < 5; wc++) {
            float v = add[wc];
            if (v >= 0.f) {
                int b; float k;
                if (kde_own(v, par, b, k)) {
                    float q = h[b], qn = q + k;
                    h[b] = qn;
                    Tr += qlogq(qn) - qlogq(q);
                    Sr += k;
                }
            }
        }
        S  += Sr;
        T2 += Tr;

        float St = S, Tt = T2;
        St += __shfl_xor_sync(0xffffffffu, St, 1);
        Tt += __shfl_xor_sync(0xffffffffu, Tt, 1);
        St += __shfl_xor_sync(0xffffffffu, St, 2);
        Tt += __shfl_xor_sync(0xffffffffu, Tt, 2);
        float Sp = St + 1e-10f;
        if (par == 0)
            o[(r0 + step) * IMG + col] = __fdividef(St * __logf(Sp) - Tt, Sp);
    }
}

extern "C" void kernel_launch(void* const* d_in, const int* in_sizes, int n_in,
                              void* d_out, int out_size) {
    const float* x = (const float*)d_in[0];
    float* out = (float*)d_out;

    cudaFuncSetAttribute(entropy_kernel,
                         cudaFuncAttributeMaxDynamicSharedMemorySize, SMEM_BYTES);

    int planes = in_sizes[0] / (IMG * IMG);   // 24
    dim3 grid(NSEG, planes);                  // (12, 24) = 288 CTAs
    entropy_kernel<<<grid, THREADS, SMEM_BYTES>>>(x, out);
}

// round 13
// speedup vs baseline: 1.4545x; 1.4545x over previous
#include <cuda_runtime.h>

// Entropy_70136815944310 — R13: byte-identical re-land of R12 (R12 failed on
// GPUAcquisitionTimeout: federation at capacity; source never executed).
// Branchless pair-split sliding window.
//
// x: [8,3,96,96] fp32 in [0,255]; out: same shape fp32.
//
// KDE kernel k(x,b) = e/(1+e)^2, e = exp(-10|x-b|), i0 = floor(x), f = x-i0.
// 4 bins i0-1..i0+2 (exact to ~1e-7; validated rel_err 3.4e-7 in R2/R5).
//   e(i0)=E=exp(-10f); e(i0+1)=G1/E; e(i0-1)=G1*E; e(i0+2)=G2/E
//   far bins (i0-1, i0+2) use k = e(1-2e), abs err < 3e-13.
//
// Pair split: thread parity par owns bins (b&1)==par. If pn = (i0 parity ==
// par): this thread's bins are {i0, i0+2}, else {i0-1, i0+1}. ALWAYS exactly
// 2 bins at stride +2 -> branchless uniform code, two provably-distinct RMWs.
//
// Edge handling without branches: redirect to pad/guard words with k=0.
// A k=0 RMW stores back what it read (value-preserving, race-benign) and its
// qlogq delta is exactly 0. Per-column layout: [0..255] bins + [256..259]
// pads; a 4-word guard before column 0 absorbs lo=-1.
//
// H = (S*log S' - T2)/S', S' = S+1e-10, T2 = sum q*log q, incremental.

#define IMG      96
#define SEG      8                    // output rows per thread pair
#define NSEG     (IMG / SEG)          // 12
#define THREADS  (IMG * 2)            // 192: lanes (2c, 2c+1) = column c
#define HSTRIDE  260                  // 256 bins + 4 pad
#define GUARD    4                    // words before hist: absorbs lo = -1
#define TROWS    (SEG + 4)            // 12
#define TCOLS    (IMG + 4)            // 100
#define NBINS    256
#define HIST_WORDS (GUARD + IMG * HSTRIDE)            // 24964 (mult of 4)
#define SMEM_BYTES ((HIST_WORDS + TROWS * TCOLS) * 4) // 104,656 B

#define G1  4.5399929762484854e-05f   // exp(-10)
#define G2  2.0611536224385578e-09f   // exp(-20)

__device__ __forceinline__ float frcp(float v) {
    float r; asm("rcp.approx.f32 %0, %1;" : "=f"(r) : "f"(v)); return r;
}
// q==0 -> 0*log(1e-37)==0 exactly; tiny negative residue -> ~1e-9, negligible
__device__ __forceinline__ float qlogq(float q) {
    return q * __logf(fmaxf(q, 1e-37f));
}

// Branchless: this thread's two bins {lo, lo+2} and masses for value v.
__device__ __forceinline__ void kde2(float v, int par,
                                     int& lo, float& klo, float& khi) {
    float fl = floorf(v);
    int   i0 = (int)fl;
    float f  = v - fl;
    bool  valid = (v >= 0.f);
    float E  = __expf(-10.f * f);
    float iE = frcp(E);
    bool  pn = ((i0 & 1) == par);
    float e_near = pn ? E : G1 * iE;         // bin i0 or i0+1
    float e_far  = pn ? G2 * iE : G1 * E;    // bin i0+2 or i0-1
    float r  = frcp(1.f + e_near);
    float kn = e_near * r * r;
    float kf = e_far * (1.f - 2.f * e_far);
    if (!valid) i0 = pn ? 256 : 257;         // sentinel -> own pads {256,258}
    lo = pn ? i0 : i0 - 1;
    float kl = pn ? kn : kf;
    float kh = pn ? kf : kn;
    klo = (valid && lo >= 0)          ? kl : 0.f;   // lo=-1 -> guard, k=0
    khi = (valid && lo + 2 <= 255)    ? kh : 0.f;   // hi=256+ -> pad, k=0
}

// Two unconditional RMWs at distinct addrs; k=0 cases are value-preserving
// and contribute exactly 0 to Sr/Tr.
__device__ __forceinline__ void apply(float* h, int lo, float klo, float khi,
                                      float& Sr, float& Tr) {
    float q0 = h[lo], q1 = h[lo + 2];
    float n0 = q0 + klo, n1 = q1 + khi;
    h[lo] = n0; h[lo + 2] = n1;
    Tr += (qlogq(n0) - qlogq(q0)) + (qlogq(n1) - qlogq(q1));
    Sr += klo + khi;
}

__global__ __launch_bounds__(THREADS, 2)
void entropy_kernel(const float* __restrict__ in, float* __restrict__ out) {
    extern __shared__ float smem[];
    float* tile = smem + HIST_WORDS;

    const int tid   = threadIdx.x;
    const int col   = tid >> 1;                    // column 0..95
    const int par   = tid & 1;                     // owns bins (b&1)==par
    const int plane = blockIdx.y;
    const int r0    = blockIdx.x * SEG;
    const float* img = in  + (size_t)plane * IMG * IMG;
    float*       o   = out + (size_t)plane * IMG * IMG;

    // ---- zero guard + all histograms + pads (float4 block-stride) ----
    {
        float4* z = (float4*)smem;
        const float4 zero = make_float4(0.f, 0.f, 0.f, 0.f);
        #pragma unroll 4
        for (int i = tid; i < HIST_WORDS / 4; i += THREADS)
            z[i] = zero;
    }

    // ---- tile: rows r0-2..r0+SEG+1, cols -2..97; OOB sentinel -10 ----
    for (int idx = tid; idx < TROWS * TCOLS; idx += THREADS) {
        int r = idx / TCOLS, c = idx % TCOLS;
        int gy = r0 + r - 2, gx = c - 2;
        float v = -10.0f;
        if ((unsigned)gy < (unsigned)IMG && (unsigned)gx < (unsigned)IMG)
            v = img[gy * IMG + gx];
        tile[idx] = v;
    }

    __syncthreads();

    float* h = smem + GUARD + col * HSTRIDE;       // 16B-aligned

    // ---- build initial histogram for y = r0 (no logs; scan follows) ----
    #pragma unroll 1
    for (int wr = 0; wr < 5; wr++) {
        const float* trow = tile + wr * TCOLS + col;
        #pragma unroll
        for (int wc = 0; wc < 5; wc++) {
            int lo; float klo, khi;
            kde2(trow[wc], par, lo, klo, khi);
            h[lo] += klo;
            h[lo + 2] += khi;
        }
    }

    // ---- initial scan: pair-partitioned interleaved float4 quads
    // (partition need not match bin ownership; pair shfl-combine totals) ----
    float S = 0.f, T2 = 0.f;
    {
        float4* h4 = (float4*)h;
        #pragma unroll 4
        for (int i = par; i < NBINS / 4; i += 2) {
            float4 q = h4[i];
            S  += (q.x + q.y) + (q.z + q.w);
            T2 += qlogq(q.x) + qlogq(q.y) + qlogq(q.z) + qlogq(q.w);
        }
    }

    {
        float St = S  + __shfl_xor_sync(0xffffffffu, S,  1);
        float Tt = T2 + __shfl_xor_sync(0xffffffffu, T2, 1);
        float Sp = St + 1e-10f;
        if (par == 0)
            o[r0 * IMG + col] = __fdividef(St * __logf(Sp) - Tt, Sp);
    }

    // ---- slide down: remove tile row step-1, add tile row step+4 ----
    #pragma unroll 1
    for (int step = 1; step < SEG; step++) {
        const float* rem = tile + (step - 1) * TCOLS + col;
        const float* add = tile + (step + 4) * TCOLS + col;

        float Sr = 0.f, Tr = 0.f;
        #pragma unroll
        for (int wc = 0; wc < 5; wc++) {
            int lo; float klo, khi;
            kde2(rem[wc], par, lo, klo, khi);
            apply(h, lo, -klo, -khi, Sr, Tr);
        }
        #pragma unroll
        for (int wc = 0; wc < 5; wc++) {
            int lo; float klo, khi;
            kde2(add[wc], par, lo, klo, khi);
            apply(h, lo, klo, khi, Sr, Tr);
        }
        S  += Sr;
        T2 += Tr;

        float St = S  + __shfl_xor_sync(0xffffffffu, S,  1);
        float Tt = T2 + __shfl_xor_sync(0xffffffffu, T2, 1);
        float Sp = St + 1e-10f;
        if (par == 0)
            o[(r0 + step) * IMG + col] = __fdividef(St * __logf(Sp) - Tt, Sp);
    }
}

extern "C" void kernel_launch(void* const* d_in, const int* in_sizes, int n_in,
                              void* d_out, int out_size) {
    const float* x = (const float*)d_in[0];
    float* out = (float*)d_out;

    cudaFuncSetAttribute(entropy_kernel,
                         cudaFuncAttributeMaxDynamicSharedMemorySize, SMEM_BYTES);

    int planes = in_sizes[0] / (IMG * IMG);   // 24
    dim3 grid(NSEG, planes);                  // (12, 24) = 288 CTAs
    entropy_kernel<<<grid, THREADS, SMEM_BYTES>>>(x, out);
}

// round 16
// speedup vs baseline: 1.7111x; 1.1764x over previous
#include <cuda_runtime.h>

// Entropy_70136815944310 — R16: byte-identical re-land of R14/R15 (two
// GPUAcquisitionTimeouts: federation at capacity; source never executed).
// R13 (27.1us, branchless pair-split sliding window) + instruction diet:
// T2 kept in log2 units (ln2 applied once at output), sign-select-before-exp
// kde2 (fewer FMUL/SEL), and batch-then-apply per slide step (10 kde evals
// pipelined into regs before the 20 ordered RMWs).
//
// x: [8,3,96,96] fp32 in [0,255]; out: same shape fp32.
//
// KDE kernel k(x,b) = e/(1+e)^2, e = exp(-10|x-b|), i0 = floor(x), f = x-i0.
// 4 bins i0-1..i0+2 (exact to ~1e-7; validated rel_err 3.3e-7).
// With w = 10f*log2(e), t = pn ? -w : +w, u = 2^t:
//   pn  (thread owns i0 parity):  e_near = u       (bin i0),
//                                 e_far  = G2/u    (bin i0+2)
//   !pn:                          e_near = G1*u    (bin i0+1),
//                                 e_far  = G1/u    (bin i0-1)
// far bins use k = e(1-2e), abs err < 3e-13.
//
// Edge handling branchless: sentinel/OOB redirected to pad/guard words with
// k=0 (value-preserving RMW, race-benign; zero S/T2 contribution).
// Layout per column: [0..255] bins + [256..259] pads; 4-word guard before
// column 0 absorbs lo=-1.
//
// T2' = sum q*lg2 q;  H = ln2 * (S*lg2(S') - T2') / S',  S' = S + 1e-10.

#define IMG      96
#define SEG      8                    // output rows per thread pair
#define NSEG     (IMG / SEG)          // 12
#define THREADS  (IMG * 2)            // 192: lanes (2c, 2c+1) = column c
#define HSTRIDE  260                  // 256 bins + 4 pad
#define GUARD    4                    // words before hist: absorbs lo = -1
#define TROWS    (SEG + 4)            // 12
#define TCOLS    (IMG + 4)            // 100
#define NBINS    256
#define HIST_WORDS (GUARD + IMG * HSTRIDE)            // 24964 (mult of 4)
#define SMEM_BYTES ((HIST_WORDS + TROWS * TCOLS) * 4) // 104,656 B

#define G1    4.5399929762484854e-05f   // exp(-10)
#define G2    2.0611536224385578e-09f   // exp(-20)
#define L2E10 14.426950408889634f       // 10 * log2(e)
#define LN2   0.6931471805599453f

__device__ __forceinline__ float frcp(float v) {
    float r; asm("rcp.approx.f32 %0, %1;" : "=f"(r) : "f"(v)); return r;
}
// q * lg2(q); q==0 -> 0*lg2(1e-37)==0 exactly; tiny negative residue guarded
__device__ __forceinline__ float qlog2q(float q) {
    return q * __log2f(fmaxf(q, 1e-37f));
}

// Branchless: this thread's two bins {lo, lo+2} and masses for value v.
__device__ __forceinline__ void kde2(float v, int par,
                                     int& lo, float& klo, float& khi) {
    float fl = floorf(v);
    int   i0 = (int)fl;
    float f  = v - fl;
    bool  valid = (v >= 0.f);
    bool  pn = ((i0 & 1) == par);
    float w  = f * L2E10;
    float t  = pn ? -w : w;
    float u  = exp2f(t);                     // MUFU.EX2
    float iu = frcp(u);
    float e_near = (pn ? 1.f : G1) * u;      // bin i0 or i0+1
    float e_far  = (pn ? G2 : G1) * iu;      // bin i0+2 or i0-1
    float r  = frcp(1.f + e_near);
    float kn = e_near * r * r;
    float kf = e_far * (1.f - 2.f * e_far);
    if (!valid) i0 = pn ? 256 : 257;         // sentinel -> own pads {256,258}
    lo = pn ? i0 : i0 - 1;
    float kl = pn ? kn : kf;
    float kh = pn ? kf : kn;
    klo = (valid && lo >= 0)       ? kl : 0.f;   // lo=-1 -> guard, k=0
    khi = (valid && lo + 2 <= 255) ? kh : 0.f;   // hi=256+ -> pad, k=0
}

// Two unconditional RMWs at distinct addrs (lo, lo+2); k=0 cases are
// value-preserving and contribute exactly 0 to Sr/Tr.
__device__ __forceinline__ void apply(float* h, int lo, float klo, float khi,
                                      float& Sr, float& Tr) {
    float q0 = h[lo], q1 = h[lo + 2];
    float n0 = q0 + klo, n1 = q1 + khi;
    h[lo] = n0; h[lo + 2] = n1;
    Tr += (qlog2q(n0) - qlog2q(q0)) + (qlog2q(n1) - qlog2q(q1));
    Sr += klo + khi;
}

__global__ __launch_bounds__(THREADS, 2)
void entropy_kernel(const float* __restrict__ in, float* __restrict__ out) {
    extern __shared__ float smem[];
    float* tile = smem + HIST_WORDS;

    const int tid   = threadIdx.x;
    const int col   = tid >> 1;                    // column 0..95
    const int par   = tid & 1;                     // owns bins (b&1)==par
    const int plane = blockIdx.y;
    const int r0    = blockIdx.x * SEG;
    const float* img = in  + (size_t)plane * IMG * IMG;
    float*       o   = out + (size_t)plane * IMG * IMG;

    // ---- zero guard + all histograms + pads (float4 block-stride) ----
    {
        float4* z = (float4*)smem;
        const float4 zero = make_float4(0.f, 0.f, 0.f, 0.f);
        #pragma unroll 4
        for (int i = tid; i < HIST_WORDS / 4; i += THREADS)
            z[i] = zero;
    }

    // ---- tile: rows r0-2..r0+SEG+1, cols -2..97; OOB sentinel -10 ----
    for (int idx = tid; idx < TROWS * TCOLS; idx += THREADS) {
        int r = idx / TCOLS, c = idx % TCOLS;
        int gy = r0 + r - 2, gx = c - 2;
        float v = -10.0f;
        if ((unsigned)gy < (unsigned)IMG && (unsigned)gx < (unsigned)IMG)
            v = img[gy * IMG + gx];
        tile[idx] = v;
    }

    __syncthreads();

    float* h = smem + GUARD + col * HSTRIDE;       // 16B-aligned

    // ---- build initial histogram for y = r0 (no logs; scan follows) ----
    #pragma unroll 1
    for (int wr = 0; wr < 5; wr++) {
        const float* trow = tile + wr * TCOLS + col;
        #pragma unroll
        for (int wc = 0; wc < 5; wc++) {
            int lo; float klo, khi;
            kde2(trow[wc], par, lo, klo, khi);
            h[lo] += klo;
            h[lo + 2] += khi;
        }
    }

    // ---- initial scan: pair-partitioned interleaved float4 quads ----
    float S = 0.f, T2 = 0.f;                       // T2 in lg2 units
    {
        float4* h4 = (float4*)h;
        #pragma unroll 4
        for (int i = par; i < NBINS / 4; i += 2) {
            float4 q = h4[i];
            S  += (q.x + q.y) + (q.z + q.w);
            T2 += qlog2q(q.x) + qlog2q(q.y) + qlog2q(q.z) + qlog2q(q.w);
        }
    }

    {
        float St = S  + __shfl_xor_sync(0xffffffffu, S,  1);
        float Tt = T2 + __shfl_xor_sync(0xffffffffu, T2, 1);
        float Sp = St + 1e-10f;
        if (par == 0)
            o[r0 * IMG + col] =
                LN2 * __fdividef(St * __log2f(Sp) - Tt, Sp);
    }

    // ---- slide down: remove tile row step-1, add tile row step+4 ----
    #pragma unroll 1
    for (int step = 1; step < SEG; step++) {
        const float* rem = tile + (step - 1) * TCOLS + col;
        const float* add = rem + 5 * TCOLS;

        // Phase 1: batch all 10 kde evals into regs (MUFUs pipeline)
        int   lo[10];
        float kl[10], kh[10];
        #pragma unroll
        for (int i = 0; i < 10; i++) {
            float v = (i < 5) ? rem[i] : add[i - 5];
            kde2(v, par, lo[i], kl[i], kh[i]);
            if (i < 5) { kl[i] = -kl[i]; kh[i] = -kh[i]; }  // folds into FADD
        }

        // Phase 2: 10 ordered RMW pairs (bins may repeat across values)
        float Sr = 0.f, Tr = 0.f;
        #pragma unroll
        for (int i = 0; i < 10; i++)
            apply(h, lo[i], kl[i], kh[i], Sr, Tr);

        S  += Sr;
        T2 += Tr;

        float St = S  + __shfl_xor_sync(0xffffffffu, S,  1);
        float Tt = T2 + __shfl_xor_sync(0xffffffffu, T2, 1);
        float Sp = St + 1e-10f;
        if (par == 0)
            o[(r0 + step) * IMG + col] =
                LN2 * __fdividef(St * __log2f(Sp) - Tt, Sp);
    }
}

extern "C" void kernel_launch(void* const* d_in, const int* in_sizes, int n_in,
                              void* d_out, int out_size) {
    const float* x = (const float*)d_in[0];
    float* out = (float*)d_out;

    cudaFuncSetAttribute(entropy_kernel,
                         cudaFuncAttributeMaxDynamicSharedMemorySize, SMEM_BYTES);

    int planes = in_sizes[0] / (IMG * IMG);   // 24
    dim3 grid(NSEG, planes);                  // (12, 24) = 288 CTAs
    entropy_kernel<<<grid, THREADS, SMEM_BYTES>>>(x, out);
}